// round 13
// baseline (speedup 1.0000x reference)
#include <cuda_runtime.h>
#include <cuda_fp16.h>
#include <cstdint>

// Problem constants
#define BATCH   4096
#define NTOK    49
#define DIM     256
#define NH      8
#define HD      32
#define MTOK    (BATCH * NTOK)      // 200704
#define QKV_N   (3 * DIM)           // 768
#define KDIM    256
#define SCALE_F 0.17677669529663687f

// Scratch (device globals)
__device__ __half g_xh[(size_t)MTOK * DIM];     // x in fp16
__device__ __half g_qkvh[(size_t)MTOK * QKV_N]; // qkv in fp16 (308 MB)
__device__ __half g_w1h[QKV_N * DIM];           // qkv_w^T fp16 [768][256]
__device__ __half g_w2h[DIM * DIM];             // proj_w^T fp16 [256][256]
__device__ __half g_biasf[16 * 7 * 256];        // bias fragment table (57344B)

// fp16 m16n8k16 mma, fp32 accumulate
__device__ __forceinline__ void mma_f16(float c[4], uint32_t a0, uint32_t a1,
                                        uint32_t a2, uint32_t a3,
                                        uint32_t b0, uint32_t b1) {
    asm volatile(
        "mma.sync.aligned.m16n8k16.row.col.f32.f16.f16.f32 "
        "{%0,%1,%2,%3},{%4,%5,%6,%7},{%8,%9},{%0,%1,%2,%3};"
        : "+f"(c[0]), "+f"(c[1]), "+f"(c[2]), "+f"(c[3])
        : "r"(a0), "r"(a1), "r"(a2), "r"(a3), "r"(b0), "r"(b1));
}

__device__ __forceinline__ void cp_async16(void* smem_dst, const void* gptr) {
    uint32_t s = (uint32_t)__cvta_generic_to_shared(smem_dst);
    asm volatile("cp.async.cg.shared.global [%0], [%1], 16;\n" :: "r"(s), "l"(gptr));
}
__device__ __forceinline__ void cp_async4(void* smem_dst, const void* gptr) {
    uint32_t s = (uint32_t)__cvta_generic_to_shared(smem_dst);
    asm volatile("cp.async.ca.shared.global [%0], [%1], 4;\n" :: "r"(s), "l"(gptr));
}
#define CP_COMMIT()  asm volatile("cp.async.commit_group;\n" ::: "memory")
#define CP_WAIT(n)   asm volatile("cp.async.wait_group %0;\n" :: "n"(n) : "memory")

__device__ __forceinline__ uint32_t pack_h2(float a, float b) {
    __half2 h = __floats2half2_rn(a, b);
    return *(uint32_t*)&h;
}

__device__ __forceinline__ void ldsm_x4(uint32_t& r0, uint32_t& r1,
                                        uint32_t& r2, uint32_t& r3,
                                        uint32_t saddr) {
    asm volatile(
        "ldmatrix.sync.aligned.m8n8.x4.shared.b16 {%0,%1,%2,%3}, [%4];"
        : "=r"(r0), "=r"(r1), "=r"(r2), "=r"(r3) : "r"(saddr));
}
__device__ __forceinline__ void ldsm_x4_trans(uint32_t& r0, uint32_t& r1,
                                              uint32_t& r2, uint32_t& r3,
                                              uint32_t saddr) {
    asm volatile(
        "ldmatrix.sync.aligned.m8n8.x4.trans.shared.b16 {%0,%1,%2,%3}, [%4];"
        : "=r"(r0), "=r"(r1), "=r"(r2), "=r"(r3) : "r"(saddr));
}

// ---------------------------------------------------------------------------
// Pre-passes
// ---------------------------------------------------------------------------
__global__ void f2h_kernel(const float* __restrict__ in, __half* __restrict__ out,
                           int n4) {
    int i = blockIdx.x * 256 + threadIdx.x;
    if (i < n4) {
        float4 v = ((const float4*)in)[i];
        __half2* o = (__half2*)out;
        o[2 * i]     = __floats2half2_rn(v.x, v.y);
        o[2 * i + 1] = __floats2half2_rn(v.z, v.w);
    }
}

// prep: w1 transpose, w2 transpose, bias FRAGMENT table
// biasf layout: [(h*2+sub)][chunk k=0..6][lane 0..31][8 halves]
//   chunk k holds e=2k (halves 0-3) and e=2k+1 (halves 4-7), e = mi*7+nt
//   slot s in 0..3: (i0,j0),(i0,j1),(i1,j0),(i1,j1)
#define PREP_N1 (DIM * QKV_N)           // 196608
#define PREP_N2 (DIM * DIM)             // 65536
#define PREP_N3 (16 * 7 * 256)          // 28672 halves
#define PREP_TOTAL (PREP_N1 + PREP_N2 + PREP_N3)

__global__ void prep_kernel(const float* __restrict__ qkv_w,
                            const float* __restrict__ proj_w,
                            const float* __restrict__ rpb,
                            __half* __restrict__ w1h, __half* __restrict__ w2h,
                            __half* __restrict__ biasf) {
    int idx = blockIdx.x * 256 + threadIdx.x;
    if (idx < PREP_N1) {
        int r = idx / QKV_N, c = idx - r * QKV_N;
        w1h[c * DIM + r] = __float2half_rn(qkv_w[idx]);
    } else if (idx < PREP_N1 + PREP_N2) {
        int t = idx - PREP_N1;
        int r = t / DIM, c = t - r * DIM;
        w2h[c * DIM + r] = __float2half_rn(proj_w[t]);
    } else if (idx < PREP_TOTAL) {
        int t = idx - PREP_N1 - PREP_N2;
        int hs   = t / 1792;
        int r    = t % 1792;
        int k    = r / 256;
        int r2   = r % 256;
        int lane = r2 / 8;
        int hidx = r2 % 8;
        int e  = 2 * k + (hidx >> 2);
        int s  = hidx & 3;
        int mi = e / 7, nt = e - mi * 7;
        int h  = hs >> 1, sub = hs & 1;
        int g  = lane >> 2, q = lane & 3;
        int i  = sub * 32 + mi * 16 + g + ((s >= 2) ? 8 : 0);
        int j  = nt * 8 + 2 * q + (s & 1);
        float val = 0.f;
        if (i < NTOK && j < NTOK) {
            int ri = i / 7, ci = i - ri * 7;
            int rj = j / 7, cj = j - rj * 7;
            int ridx = (ri - rj + 6) * 13 + (ci - cj + 6);
            val = rpb[ridx * NH + h];
        }
        biasf[t] = __float2half_rn(val);
    }
}

// ---------------------------------------------------------------------------
// FP16 QKV GEMM (R9 proven form, unchanged)
// ---------------------------------------------------------------------------
#define BKH 32
#define TILE_BYTES (128 * 64)
#define STAGE_BYTES (2 * TILE_BYTES)
#define HSTAGES 4
#define GEMM_SMEM_H (HSTAGES * STAGE_BYTES)

__global__ __launch_bounds__(256, 2) void gemm_h(
    const __half* __restrict__ A, const __half* __restrict__ BT,
    const float* __restrict__ bias, __half* __restrict__ C, int N)
{
    extern __shared__ __align__(128) char smem[];

    const int tid  = threadIdx.x;
    const int lane = tid & 31;
    const int warp = tid >> 5;
    const int wm   = warp & 1;
    const int wn   = warp >> 1;
    const int bm   = blockIdx.y * 128;
    const int bn   = blockIdx.x * 128;
    const int tig  = lane & 3;
    const int grp  = lane >> 2;

    float c[4][4][4];
    #pragma unroll
    for (int mi = 0; mi < 4; mi++)
        #pragma unroll
        for (int ni = 0; ni < 4; ni++)
            #pragma unroll
            for (int r = 0; r < 4; r++) c[mi][ni][r] = 0.f;

    auto load_stage = [&](int slot, int kt) {
        char* ab = smem + slot * STAGE_BYTES;
        char* bb = ab + TILE_BYTES;
        const __half* ag = A  + (size_t)bm * KDIM + kt * BKH;
        const __half* bg = BT + (size_t)bn * KDIM + kt * BKH;
        #pragma unroll
        for (int j = 0; j < 2; j++) {
            int sgi = tid + j * 256;
            int r   = sgi >> 2;
            int cc  = sgi & 3;
            cp_async16(ab + r * 64 + cc * 16, ag + (size_t)r * KDIM + cc * 8);
            cp_async16(bb + r * 64 + cc * 16, bg + (size_t)r * KDIM + cc * 8);
        }
    };

    const int ITERS = KDIM / BKH;
    #pragma unroll
    for (int p = 0; p < HSTAGES - 1; p++) { load_stage(p, p); CP_COMMIT(); }

    for (int it = 0; it < ITERS; it++) {
        CP_WAIT(HSTAGES - 2);
        __syncthreads();

        int nk = it + HSTAGES - 1;
        if (nk < ITERS) load_stage(nk & (HSTAGES - 1), nk);
        CP_COMMIT();

        const char* as = smem + (it & (HSTAGES - 1)) * STAGE_BYTES;
        const char* bs = as + TILE_BYTES;

        uint4 ra[4], rb[4];
        #pragma unroll
        for (int mi = 0; mi < 4; mi++) {
            int row = wm * 64 + mi * 16 + grp;
            ra[mi] = *(const uint4*)(as + row * 64 + tig * 16);
            rb[mi] = *(const uint4*)(as + (row + 8) * 64 + tig * 16);
        }
        #pragma unroll
        for (int ni = 0; ni < 4; ni++) {
            int col = wn * 32 + ni * 8 + grp;
            uint4 sb = *(const uint4*)(bs + col * 64 + tig * 16);
            #pragma unroll
            for (int mi = 0; mi < 4; mi++) {
                mma_f16(c[mi][ni], ra[mi].x, rb[mi].x, ra[mi].y, rb[mi].y, sb.x, sb.y);
                mma_f16(c[mi][ni], ra[mi].z, rb[mi].z, ra[mi].w, rb[mi].w, sb.z, sb.w);
            }
        }
    }

    #pragma unroll
    for (int mi = 0; mi < 4; mi++) {
        int row0 = bm + wm * 64 + mi * 16 + grp;
        #pragma unroll
        for (int ni = 0; ni < 4; ni++) {
            int col0 = bn + wn * 32 + ni * 8 + tig * 2;
            float bi0 = bias[col0], bi1 = bias[col0 + 1];
            *(__half2*)(C + (size_t)row0 * N + col0) =
                __floats2half2_rn(c[mi][ni][0] + bi0, c[mi][ni][1] + bi1);
            *(__half2*)(C + (size_t)(row0 + 8) * N + col0) =
                __floats2half2_rn(c[mi][ni][2] + bi0, c[mi][ni][3] + bi1);
        }
    }
}

// ---------------------------------------------------------------------------
// Persistent fused attention + projection: grid = #SMs, 512 threads.
// Each block loops over windows (stride gridDim.x), double-buffering the
// per-window inputs (QKV + mask) via cp.async so window w+1's load overlaps
// window w's compute. AO aliases the current buffer's dead Q/K region.
// Bias comes from a global fragment-ordered table (L1-hot, persistent).
// ---------------------------------------------------------------------------
#define QKV_STRIDE 528
#define QOFF_B 0
#define KOFF_B 33792                    // Q: 64 rows
#define VOFF_B (KOFF_B + 56 * QKV_STRIDE)  // K: 56 rows -> 63360
#define MOFF_B (VOFF_B + 64 * QKV_STRIDE)  // V: 64 rows -> 97152
#define BUF_BYTES 106880                // 97152 + 9616 mask, 128-aligned
#define AO_STRIDE 576
#define FUSE_SMEM (2 * BUF_BYTES)       // 213760

__global__ __launch_bounds__(512, 1) void attn_proj_fused(
    const __half* __restrict__ qkv, const float* __restrict__ mask,
    const __half* __restrict__ biasf, const __half* __restrict__ w2,
    const float* __restrict__ proj_b, float* __restrict__ out)
{
    extern __shared__ __align__(128) char sm[];
    const uint32_t sbase = (uint32_t)__cvta_generic_to_shared(sm);

    const int tid  = threadIdx.x;
    const int lane = tid & 31;
    const int wid  = tid >> 5;
    const int g    = lane >> 2;     // 0..7
    const int q    = lane & 3;      // 0..3
    const int h    = wid >> 1;
    const int sub  = wid & 1;
    const int hoff = h * 64;

    auto prefetch = [&](int buf, int w) {
        char* base = sm + buf * BUF_BYTES;
        const __half* src = qkv + (size_t)w * NTOK * QKV_N;
        for (int idx = tid; idx < NTOK * 96; idx += 512) {
            int tok = idx / 96, c16 = idx - tok * 96;
            int seg = c16 >> 5;
            int segoff = (seg == 0) ? QOFF_B : (seg == 1) ? KOFF_B : VOFF_B;
            cp_async16(base + segoff + tok * QKV_STRIDE + (c16 & 31) * 16,
                       src + (size_t)tok * QKV_N + c16 * 8);
        }
        const float* mrow = mask + (size_t)w * NTOK * NTOK;
        for (int idx = tid; idx < NTOK * NTOK; idx += 512)
            cp_async4(base + MOFF_B + idx * 4, mrow + idx);
    };

    // Prologue: prefetch first window; zero V pad rows of both buffers
    int w0 = blockIdx.x;
    if (w0 < BATCH) prefetch(0, w0);
    CP_COMMIT();
    for (int idx = tid; idx < 2 * 15 * 132; idx += 512) {
        int buf = idx / (15 * 132);
        int rem = idx - buf * (15 * 132);
        int r = rem / 132, wd = rem - r * 132;
        *(uint32_t*)(sm + buf * BUF_BYTES + VOFF_B + (NTOK + r) * QKV_STRIDE + wd * 4) = 0;
    }

    const char* bfp = (const char*)biasf + (h * 2 + sub) * 3584 + lane * 16;

    int cur = 0;
    for (int w = w0; w < BATCH; w += gridDim.x, cur ^= 1) {
        int wnext = w + gridDim.x;
        if (wnext < BATCH) prefetch(cur ^ 1, wnext);
        CP_COMMIT();
        CP_WAIT(1);                 // window w's group complete
        __syncthreads();

        const char* base = sm + cur * BUF_BYTES;
        const uint32_t baseu = sbase + cur * BUF_BYTES;

        // ---- Phase 2: S = Q*K^T
        float c[2][7][4];
        #pragma unroll
        for (int mi = 0; mi < 2; mi++)
            #pragma unroll
            for (int nt = 0; nt < 7; nt++)
                #pragma unroll
                for (int r = 0; r < 4; r++) c[mi][nt][r] = 0.f;

        uint32_t afr[2][2][4];
        #pragma unroll
        for (int mi = 0; mi < 2; mi++) {
            int r0 = sub * 32 + mi * 16;
            #pragma unroll
            for (int cc = 0; cc < 2; cc++) {
                uint32_t addr = baseu + QOFF_B
                              + (uint32_t)(r0 + (lane & 15)) * QKV_STRIDE
                              + hoff + cc * 32 + ((lane >> 4) * 16);
                ldsm_x4(afr[mi][cc][0], afr[mi][cc][1],
                        afr[mi][cc][2], afr[mi][cc][3], addr);
            }
        }
        #pragma unroll
        for (int nt = 0; nt < 7; nt++) {
            uint32_t kaddr = baseu + KOFF_B
                           + (uint32_t)(nt * 8 + (lane & 7)) * QKV_STRIDE
                           + hoff + ((lane >> 3) * 16);
            uint32_t b0, b1, b2, b3;
            ldsm_x4(b0, b1, b2, b3, kaddr);
            #pragma unroll
            for (int mi = 0; mi < 2; mi++) {
                mma_f16(c[mi][nt], afr[mi][0][0], afr[mi][0][1],
                        afr[mi][0][2], afr[mi][0][3], b0, b1);
                mma_f16(c[mi][nt], afr[mi][1][0], afr[mi][1][1],
                        afr[mi][1][2], afr[mi][1][3], b2, b3);
            }
        }

        // ---- Phase 3: scale + bias(frag LDG) + mask(smem) + reg softmax
        const float* mrow_s = (const float*)(base + MOFF_B);
        float inv0[2], inv1[2];
        #pragma unroll
        for (int mi = 0; mi < 2; mi++) {
            int i0 = sub * 32 + mi * 16 + g;
            int i1 = i0 + 8;
            bool vi0 = i0 < NTOK, vi1 = i1 < NTOK;
            int c0c = (mi * 7) >> 1;        // base chunk: 0 or 3
            uint4 bb[4];
            #pragma unroll
            for (int k = 0; k < 4; k++)
                bb[k] = *(const uint4*)(bfp + (c0c + k) * 512);
            #pragma unroll
            for (int nt = 0; nt < 7; nt++) {
                int e = mi * 7 + nt;
                const uint4& B = bb[(e >> 1) - c0c];
                uint32_t u0 = (e & 1) ? B.z : B.x;
                uint32_t u1 = (e & 1) ? B.w : B.y;
                float2 bf0 = __half22float2(*reinterpret_cast<__half2*>(&u0));
                float2 bf1 = __half22float2(*reinterpret_cast<__half2*>(&u1));
                int j0 = nt * 8 + 2 * q, j1 = j0 + 1;
                bool vj0 = j0 < NTOK, vj1 = j1 < NTOK;
                c[mi][nt][0] = (vi0 && vj0) ? c[mi][nt][0] * SCALE_F + bf0.x + mrow_s[i0 * NTOK + j0] : -1e30f;
                c[mi][nt][1] = (vi0 && vj1) ? c[mi][nt][1] * SCALE_F + bf0.y + mrow_s[i0 * NTOK + j1] : -1e30f;
                c[mi][nt][2] = (vi1 && vj0) ? c[mi][nt][2] * SCALE_F + bf1.x + mrow_s[i1 * NTOK + j0] : -1e30f;
                c[mi][nt][3] = (vi1 && vj1) ? c[mi][nt][3] * SCALE_F + bf1.y + mrow_s[i1 * NTOK + j1] : -1e30f;
            }
            float m0 = -1e30f, m1 = -1e30f;
            #pragma unroll
            for (int nt = 0; nt < 7; nt++) {
                m0 = fmaxf(m0, fmaxf(c[mi][nt][0], c[mi][nt][1]));
                m1 = fmaxf(m1, fmaxf(c[mi][nt][2], c[mi][nt][3]));
            }
            m0 = fmaxf(m0, __shfl_xor_sync(0xffffffffu, m0, 1));
            m0 = fmaxf(m0, __shfl_xor_sync(0xffffffffu, m0, 2));
            m1 = fmaxf(m1, __shfl_xor_sync(0xffffffffu, m1, 1));
            m1 = fmaxf(m1, __shfl_xor_sync(0xffffffffu, m1, 2));
            float s0 = 0.f, s1 = 0.f;
            #pragma unroll
            for (int nt = 0; nt < 7; nt++) {
                c[mi][nt][0] = __expf(c[mi][nt][0] - m0); s0 += c[mi][nt][0];
                c[mi][nt][1] = __expf(c[mi][nt][1] - m0); s0 += c[mi][nt][1];
                c[mi][nt][2] = __expf(c[mi][nt][2] - m1); s1 += c[mi][nt][2];
                c[mi][nt][3] = __expf(c[mi][nt][3] - m1); s1 += c[mi][nt][3];
            }
            s0 += __shfl_xor_sync(0xffffffffu, s0, 1);
            s0 += __shfl_xor_sync(0xffffffffu, s0, 2);
            s1 += __shfl_xor_sync(0xffffffffu, s1, 1);
            s1 += __shfl_xor_sync(0xffffffffu, s1, 2);
            inv0[mi] = 1.f / s0;
            inv1[mi] = 1.f / s1;
        }

        // ---- Pack P into fp16 A-fragments
        uint32_t pa[2][4][4];
        #pragma unroll
        for (int mi = 0; mi < 2; mi++) {
            #pragma unroll
            for (int ch = 0; ch < 4; ch++) {
                int nt0 = 2 * ch, nt1 = 2 * ch + 1;
                pa[mi][ch][0] = pack_h2(c[mi][nt0][0] * inv0[mi], c[mi][nt0][1] * inv0[mi]);
                pa[mi][ch][1] = pack_h2(c[mi][nt0][2] * inv1[mi], c[mi][nt0][3] * inv1[mi]);
                if (nt1 < 7) {
                    pa[mi][ch][2] = pack_h2(c[mi][nt1][0] * inv0[mi], c[mi][nt1][1] * inv0[mi]);
                    pa[mi][ch][3] = pack_h2(c[mi][nt1][2] * inv1[mi], c[mi][nt1][3] * inv1[mi]);
                } else {
                    pa[mi][ch][2] = 0u;
                    pa[mi][ch][3] = 0u;
                }
            }
        }

        // All Q/K reads done before AO (aliasing Q/K) is written
        __syncthreads();

        // ---- Phase 4: PV mma; AO rows into current buffer's Q/K region
        #pragma unroll
        for (int mi = 0; mi < 2; mi++) {
            int i0 = sub * 32 + mi * 16 + g;
            int i1 = i0 + 8;
            #pragma unroll
            for (int ni = 0; ni < 4; ni++) {
                float o[4] = {0.f, 0.f, 0.f, 0.f};
                #pragma unroll
                for (int hf = 0; hf < 2; hf++) {
                    uint32_t addr = baseu + VOFF_B
                                  + (uint32_t)(hf * 32 + lane) * QKV_STRIDE
                                  + hoff + ni * 16;
                    uint32_t r0, r1, r2, r3;
                    ldsm_x4_trans(r0, r1, r2, r3, addr);
                    mma_f16(o, pa[mi][2 * hf][0], pa[mi][2 * hf][1],
                            pa[mi][2 * hf][2], pa[mi][2 * hf][3], r0, r1);
                    mma_f16(o, pa[mi][2 * hf + 1][0], pa[mi][2 * hf + 1][1],
                            pa[mi][2 * hf + 1][2], pa[mi][2 * hf + 1][3], r2, r3);
                }
                int colb = (h * 32 + ni * 8) * 2 + q * 4;
                *(uint32_t*)(base + (size_t)i0 * AO_STRIDE + colb) = pack_h2(o[0], o[1]);
                *(uint32_t*)(base + (size_t)i1 * AO_STRIDE + colb) = pack_h2(o[2], o[3]);
            }
        }
        __syncthreads();

        // ---- Phase 5: proj GEMM [64x256] = AO x W2^T (global w2 LDG, R9 form)
        const int wm   = wid & 1;
        const int wcol = wid >> 1;
        float d[2][4][4];
        #pragma unroll
        for (int mi = 0; mi < 2; mi++)
            #pragma unroll
            for (int ni = 0; ni < 4; ni++)
                #pragma unroll
                for (int r = 0; r < 4; r++) d[mi][ni][r] = 0.f;

        #pragma unroll
        for (int cp = 0; cp < 8; cp++) {
            uint4 ra[2], rb[2];
            #pragma unroll
            for (int mi = 0; mi < 2; mi++) {
                int r0 = wm * 32 + mi * 16 + g;
                ra[mi] = *(const uint4*)(base + (size_t)r0 * AO_STRIDE + cp * 64 + q * 16);
                rb[mi] = *(const uint4*)(base + (size_t)(r0 + 8) * AO_STRIDE + cp * 64 + q * 16);
            }
            #pragma unroll
            for (int ni = 0; ni < 4; ni++) {
                int n = wcol * 32 + ni * 8 + g;
                uint4 sb = *(const uint4*)(w2 + (size_t)n * KDIM + cp * 32 + q * 8);
                #pragma unroll
                for (int mi = 0; mi < 2; mi++) {
                    mma_f16(d[mi][ni], ra[mi].x, rb[mi].x, ra[mi].y, rb[mi].y, sb.x, sb.y);
                    mma_f16(d[mi][ni], ra[mi].z, rb[mi].z, ra[mi].w, rb[mi].w, sb.z, sb.w);
                }
            }
        }

        // ---- Epilogue: + proj_b, fp32 out
        #pragma unroll
        for (int mi = 0; mi < 2; mi++) {
            int i0 = wm * 32 + mi * 16 + g;
            int i1 = i0 + 8;
            #pragma unroll
            for (int ni = 0; ni < 4; ni++) {
                int n0 = wcol * 32 + ni * 8 + 2 * q;
                float2 pb = *(const float2*)(proj_b + n0);
                if (i0 < NTOK) {
                    float2 v = make_float2(d[mi][ni][0] + pb.x, d[mi][ni][1] + pb.y);
                    *(float2*)(out + ((size_t)w * NTOK + i0) * DIM + n0) = v;
                }
                if (i1 < NTOK) {
                    float2 v = make_float2(d[mi][ni][2] + pb.x, d[mi][ni][3] + pb.y);
                    *(float2*)(out + ((size_t)w * NTOK + i1) * DIM + n0) = v;
                }
            }
        }

        __syncthreads();   // AO reads done before next iter overwrites cur buffer
    }
}

// ---------------------------------------------------------------------------
extern "C" void kernel_launch(void* const* d_in, const int* in_sizes, int n_in,
                              void* d_out, int out_size)
{
    const float* x      = (const float*)d_in[0];
    const float* mask   = (const float*)d_in[1];
    const float* qkv_w  = (const float*)d_in[2];
    const float* qkv_b  = (const float*)d_in[3];
    const float* rpb    = (const float*)d_in[4];
    const float* proj_w = (const float*)d_in[5];
    const float* proj_b = (const float*)d_in[6];
    float* out = (float*)d_out;

    __half *xh, *qkvh, *w1h, *w2h, *biasf;
    cudaGetSymbolAddress((void**)&xh, g_xh);
    cudaGetSymbolAddress((void**)&qkvh, g_qkvh);
    cudaGetSymbolAddress((void**)&w1h, g_w1h);
    cudaGetSymbolAddress((void**)&w2h, g_w2h);
    cudaGetSymbolAddress((void**)&biasf, g_biasf);

    cudaFuncSetAttribute(gemm_h,
                         cudaFuncAttributeMaxDynamicSharedMemorySize, GEMM_SMEM_H);
    cudaFuncSetAttribute(attn_proj_fused,
                         cudaFuncAttributeMaxDynamicSharedMemorySize, FUSE_SMEM);

    int dev = 0, nsm = 148;
    cudaGetDevice(&dev);
    cudaDeviceGetAttribute(&nsm, cudaDevAttrMultiProcessorCount, dev);

    // 0) Pre-passes
    int n4 = MTOK * DIM / 4;
    f2h_kernel<<<(n4 + 255) / 256, 256>>>(x, xh, n4);
    prep_kernel<<<(PREP_TOTAL + 255) / 256, 256>>>(qkv_w, proj_w, rpb,
                                                   w1h, w2h, biasf);

    // 1) QKV GEMM (fp16)
    gemm_h<<<dim3(QKV_N / 128, MTOK / 128), 256, GEMM_SMEM_H>>>(
        xh, w1h, qkv_b, qkvh, QKV_N);

    // 2) Persistent fused attention + projection (fp32 out)
    attn_proj_fused<<<nsm, 512, FUSE_SMEM>>>(
        qkvh, mask, biasf, w2h, proj_b, out);
}

// round 14
// speedup vs baseline: 1.4762x; 1.4762x over previous
#include <cuda_runtime.h>
#include <cuda_fp16.h>
#include <cstdint>

// Problem constants
#define BATCH   4096
#define NTOK    49
#define DIM     256
#define NH      8
#define HD      32
#define MTOK    (BATCH * NTOK)      // 200704
#define QKV_N   (3 * DIM)           // 768
#define KDIM    256
#define SCALE_F 0.17677669529663687f

// Scratch (device globals)
__device__ __half g_xh[(size_t)MTOK * DIM];     // x in fp16
__device__ __half g_qkvh[(size_t)MTOK * QKV_N]; // qkv in fp16 (308 MB)
__device__ __half g_w1h[QKV_N * DIM];           // qkv_w^T fp16 [768][256]
__device__ __half g_w2h[DIM * DIM];             // proj_w^T fp16 [256][256]
__device__ __half g_biasf[16 * 7 * 256];        // bias fragment table (57344B)

// fp16 m16n8k16 mma, fp32 accumulate
__device__ __forceinline__ void mma_f16(float c[4], uint32_t a0, uint32_t a1,
                                        uint32_t a2, uint32_t a3,
                                        uint32_t b0, uint32_t b1) {
    asm volatile(
        "mma.sync.aligned.m16n8k16.row.col.f32.f16.f16.f32 "
        "{%0,%1,%2,%3},{%4,%5,%6,%7},{%8,%9},{%0,%1,%2,%3};"
        : "+f"(c[0]), "+f"(c[1]), "+f"(c[2]), "+f"(c[3])
        : "r"(a0), "r"(a1), "r"(a2), "r"(a3), "r"(b0), "r"(b1));
}

__device__ __forceinline__ void cp_async16(void* smem_dst, const void* gptr) {
    uint32_t s = (uint32_t)__cvta_generic_to_shared(smem_dst);
    asm volatile("cp.async.cg.shared.global [%0], [%1], 16;\n" :: "r"(s), "l"(gptr));
}
__device__ __forceinline__ void cp_async4(void* smem_dst, const void* gptr) {
    uint32_t s = (uint32_t)__cvta_generic_to_shared(smem_dst);
    asm volatile("cp.async.ca.shared.global [%0], [%1], 4;\n" :: "r"(s), "l"(gptr));
}
#define CP_COMMIT()  asm volatile("cp.async.commit_group;\n" ::: "memory")
#define CP_WAIT(n)   asm volatile("cp.async.wait_group %0;\n" :: "n"(n) : "memory")

__device__ __forceinline__ uint32_t pack_h2(float a, float b) {
    __half2 h = __floats2half2_rn(a, b);
    return *(uint32_t*)&h;
}

__device__ __forceinline__ void ldsm_x4(uint32_t& r0, uint32_t& r1,
                                        uint32_t& r2, uint32_t& r3,
                                        uint32_t saddr) {
    asm volatile(
        "ldmatrix.sync.aligned.m8n8.x4.shared.b16 {%0,%1,%2,%3}, [%4];"
        : "=r"(r0), "=r"(r1), "=r"(r2), "=r"(r3) : "r"(saddr));
}
__device__ __forceinline__ void ldsm_x4_trans(uint32_t& r0, uint32_t& r1,
                                              uint32_t& r2, uint32_t& r3,
                                              uint32_t saddr) {
    asm volatile(
        "ldmatrix.sync.aligned.m8n8.x4.trans.shared.b16 {%0,%1,%2,%3}, [%4];"
        : "=r"(r0), "=r"(r1), "=r"(r2), "=r"(r3) : "r"(saddr));
}

// ---------------------------------------------------------------------------
// Pre-passes
// ---------------------------------------------------------------------------
__global__ void f2h_kernel(const float* __restrict__ in, __half* __restrict__ out,
                           int n4) {
    int i = blockIdx.x * 256 + threadIdx.x;
    if (i < n4) {
        float4 v = ((const float4*)in)[i];
        __half2* o = (__half2*)out;
        o[2 * i]     = __floats2half2_rn(v.x, v.y);
        o[2 * i + 1] = __floats2half2_rn(v.z, v.w);
    }
}

// prep: w1 transpose, w2 transpose, bias FRAGMENT table (validated in R13)
// biasf layout: [(h*2+sub)][chunk k=0..6][lane 0..31][8 halves]
//   chunk k holds e=2k (halves 0-3) and e=2k+1 (halves 4-7), e = mi*7+nt
//   slot s in 0..3: (i0,j0),(i0,j1),(i1,j0),(i1,j1)
#define PREP_N1 (DIM * QKV_N)           // 196608
#define PREP_N2 (DIM * DIM)             // 65536
#define PREP_N3 (16 * 7 * 256)          // 28672 halves
#define PREP_TOTAL (PREP_N1 + PREP_N2 + PREP_N3)

__global__ void prep_kernel(const float* __restrict__ qkv_w,
                            const float* __restrict__ proj_w,
                            const float* __restrict__ rpb,
                            __half* __restrict__ w1h, __half* __restrict__ w2h,
                            __half* __restrict__ biasf) {
    int idx = blockIdx.x * 256 + threadIdx.x;
    if (idx < PREP_N1) {
        int r = idx / QKV_N, c = idx - r * QKV_N;
        w1h[c * DIM + r] = __float2half_rn(qkv_w[idx]);
    } else if (idx < PREP_N1 + PREP_N2) {
        int t = idx - PREP_N1;
        int r = t / DIM, c = t - r * DIM;
        w2h[c * DIM + r] = __float2half_rn(proj_w[t]);
    } else if (idx < PREP_TOTAL) {
        int t = idx - PREP_N1 - PREP_N2;
        int hs   = t / 1792;
        int r    = t % 1792;
        int k    = r / 256;
        int r2   = r % 256;
        int lane = r2 / 8;
        int hidx = r2 % 8;
        int e  = 2 * k + (hidx >> 2);
        int s  = hidx & 3;
        int mi = e / 7, nt = e - mi * 7;
        int h  = hs >> 1, sub = hs & 1;
        int g  = lane >> 2, q = lane & 3;
        int i  = sub * 32 + mi * 16 + g + ((s >= 2) ? 8 : 0);
        int j  = nt * 8 + 2 * q + (s & 1);
        float val = 0.f;
        if (i < NTOK && j < NTOK) {
            int ri = i / 7, ci = i - ri * 7;
            int rj = j / 7, cj = j - rj * 7;
            int ridx = (ri - rj + 6) * 13 + (ci - cj + 6);
            val = rpb[ridx * NH + h];
        }
        biasf[t] = __float2half_rn(val);
    }
}

// ---------------------------------------------------------------------------
// FP16 QKV GEMM (R9 proven form, unchanged)
// ---------------------------------------------------------------------------
#define BKH 32
#define TILE_BYTES (128 * 64)
#define STAGE_BYTES (2 * TILE_BYTES)
#define HSTAGES 4
#define GEMM_SMEM_H (HSTAGES * STAGE_BYTES)

__global__ __launch_bounds__(256, 2) void gemm_h(
    const __half* __restrict__ A, const __half* __restrict__ BT,
    const float* __restrict__ bias, __half* __restrict__ C, int N)
{
    extern __shared__ __align__(128) char smem[];

    const int tid  = threadIdx.x;
    const int lane = tid & 31;
    const int warp = tid >> 5;
    const int wm   = warp & 1;
    const int wn   = warp >> 1;
    const int bm   = blockIdx.y * 128;
    const int bn   = blockIdx.x * 128;
    const int tig  = lane & 3;
    const int grp  = lane >> 2;

    float c[4][4][4];
    #pragma unroll
    for (int mi = 0; mi < 4; mi++)
        #pragma unroll
        for (int ni = 0; ni < 4; ni++)
            #pragma unroll
            for (int r = 0; r < 4; r++) c[mi][ni][r] = 0.f;

    auto load_stage = [&](int slot, int kt) {
        char* ab = smem + slot * STAGE_BYTES;
        char* bb = ab + TILE_BYTES;
        const __half* ag = A  + (size_t)bm * KDIM + kt * BKH;
        const __half* bg = BT + (size_t)bn * KDIM + kt * BKH;
        #pragma unroll
        for (int j = 0; j < 2; j++) {
            int sgi = tid + j * 256;
            int r   = sgi >> 2;
            int cc  = sgi & 3;
            cp_async16(ab + r * 64 + cc * 16, ag + (size_t)r * KDIM + cc * 8);
            cp_async16(bb + r * 64 + cc * 16, bg + (size_t)r * KDIM + cc * 8);
        }
    };

    const int ITERS = KDIM / BKH;
    #pragma unroll
    for (int p = 0; p < HSTAGES - 1; p++) { load_stage(p, p); CP_COMMIT(); }

    for (int it = 0; it < ITERS; it++) {
        CP_WAIT(HSTAGES - 2);
        __syncthreads();

        int nk = it + HSTAGES - 1;
        if (nk < ITERS) load_stage(nk & (HSTAGES - 1), nk);
        CP_COMMIT();

        const char* as = smem + (it & (HSTAGES - 1)) * STAGE_BYTES;
        const char* bs = as + TILE_BYTES;

        uint4 ra[4], rb[4];
        #pragma unroll
        for (int mi = 0; mi < 4; mi++) {
            int row = wm * 64 + mi * 16 + grp;
            ra[mi] = *(const uint4*)(as + row * 64 + tig * 16);
            rb[mi] = *(const uint4*)(as + (row + 8) * 64 + tig * 16);
        }
        #pragma unroll
        for (int ni = 0; ni < 4; ni++) {
            int col = wn * 32 + ni * 8 + grp;
            uint4 sb = *(const uint4*)(bs + col * 64 + tig * 16);
            #pragma unroll
            for (int mi = 0; mi < 4; mi++) {
                mma_f16(c[mi][ni], ra[mi].x, rb[mi].x, ra[mi].y, rb[mi].y, sb.x, sb.y);
                mma_f16(c[mi][ni], ra[mi].z, rb[mi].z, ra[mi].w, rb[mi].w, sb.z, sb.w);
            }
        }
    }

    #pragma unroll
    for (int mi = 0; mi < 4; mi++) {
        int row0 = bm + wm * 64 + mi * 16 + grp;
        #pragma unroll
        for (int ni = 0; ni < 4; ni++) {
            int col0 = bn + wn * 32 + ni * 8 + tig * 2;
            float bi0 = bias[col0], bi1 = bias[col0 + 1];
            *(__half2*)(C + (size_t)row0 * N + col0) =
                __floats2half2_rn(c[mi][ni][0] + bi0, c[mi][ni][1] + bi1);
            *(__half2*)(C + (size_t)(row0 + 8) * N + col0) =
                __floats2half2_rn(c[mi][ni][2] + bi0, c[mi][ni][3] + bi1);
        }
    }
}

// ---------------------------------------------------------------------------
// Fused attention + projection v6 (R9 skeleton): one block per window, 512 thr.
// Changes vs R9: bias via global fragment table (no 38KB smem staging);
// mask staged PADDED [64][56] with -1e30 pads -> no validity ternaries.
// ---------------------------------------------------------------------------
#define QKV_STRIDE 528
#define REG_BYTES  (64 * QKV_STRIDE)    // 33792 per region
#define QOFF   0
#define KOFF   REG_BYTES
#define VOFF   (2 * REG_BYTES)
#define AOOFF  (3 * REG_BYTES)          // 101376
#define AO_STRIDE 576
#define MOFF   (AOOFF + 64 * AO_STRIDE) // 138240
#define MSTRIDE 224                     // 56 floats per padded mask row
#define FUSE_SMEM (MOFF + 64 * MSTRIDE) // 152576

__global__ __launch_bounds__(512, 1) void attn_proj_fused(
    const __half* __restrict__ qkv, const float* __restrict__ mask,
    const __half* __restrict__ biasf, const __half* __restrict__ w2,
    const float* __restrict__ proj_b, float* __restrict__ out)
{
    extern __shared__ __align__(128) char sm[];
    const uint32_t sbase = (uint32_t)__cvta_generic_to_shared(sm);

    const int b    = blockIdx.x;
    const int tid  = threadIdx.x;
    const int lane = tid & 31;
    const int wid  = tid >> 5;
    const int g    = lane >> 2;     // 0..7
    const int q    = lane & 3;      // 0..3

    // ---- Phase 1: async loads (qkv rows, padded mask)
    {
        const __half* src = qkv + (size_t)b * NTOK * QKV_N;
        for (int idx = tid; idx < NTOK * 96; idx += 512) {
            int tok = idx / 96, c16 = idx - tok * 96;
            int seg = c16 >> 5;                  // 0=q 1=k 2=v
            int off = (c16 & 31) * 16;
            cp_async16(sm + seg * REG_BYTES + tok * QKV_STRIDE + off,
                       src + (size_t)tok * QKV_N + c16 * 8);
        }
        const float* mrow = mask + (size_t)b * NTOK * NTOK;
        for (int idx = tid; idx < NTOK * NTOK; idx += 512) {
            int i = idx / NTOK, j = idx - i * NTOK;
            cp_async4(sm + MOFF + i * MSTRIDE + j * 4, mrow + idx);
        }
        CP_COMMIT();
    }
    // While loads fly: zero Q/K/V pad rows; fill mask pads with -1e30
    for (int idx = tid; idx < 3 * 15 * 132; idx += 512) {
        int reg = idx / (15 * 132);
        int rem = idx - reg * (15 * 132);
        int r = rem / 132, w = rem - r * 132;
        *(uint32_t*)(sm + reg * REG_BYTES + (NTOK + r) * QKV_STRIDE + w * 4) = 0;
    }
    for (int idx = tid; idx < 64 * 56; idx += 512) {
        int i = idx / 56, j = idx - i * 56;
        if (i >= NTOK || j >= NTOK)
            *(float*)(sm + MOFF + i * MSTRIDE + j * 4) = -1e30f;
    }
    CP_WAIT(0);
    __syncthreads();

    // ---- Phase 2: S = Q*K^T per warp (head h, rows [sub*32, sub*32+32))
    const int h   = wid >> 1;
    const int sub = wid & 1;
    const int hoff = h * 64;

    float c[2][7][4];
    #pragma unroll
    for (int mi = 0; mi < 2; mi++)
        #pragma unroll
        for (int nt = 0; nt < 7; nt++)
            #pragma unroll
            for (int r = 0; r < 4; r++) c[mi][nt][r] = 0.f;

    uint32_t afr[2][2][4];
    #pragma unroll
    for (int mi = 0; mi < 2; mi++) {
        int r0 = sub * 32 + mi * 16;
        #pragma unroll
        for (int cc = 0; cc < 2; cc++) {
            uint32_t addr = sbase + QOFF + (uint32_t)(r0 + (lane & 15)) * QKV_STRIDE
                          + hoff + cc * 32 + ((lane >> 4) * 16);
            ldsm_x4(afr[mi][cc][0], afr[mi][cc][1], afr[mi][cc][2], afr[mi][cc][3], addr);
        }
    }
    #pragma unroll
    for (int nt = 0; nt < 7; nt++) {
        uint32_t kaddr = sbase + KOFF + (uint32_t)(nt * 8 + (lane & 7)) * QKV_STRIDE
                       + hoff + ((lane >> 3) * 16);
        uint32_t b0, b1, b2, b3;
        ldsm_x4(b0, b1, b2, b3, kaddr);
        #pragma unroll
        for (int mi = 0; mi < 2; mi++) {
            mma_f16(c[mi][nt], afr[mi][0][0], afr[mi][0][1],
                    afr[mi][0][2], afr[mi][0][3], b0, b1);
            mma_f16(c[mi][nt], afr[mi][1][0], afr[mi][1][1],
                    afr[mi][1][2], afr[mi][1][3], b2, b3);
        }
    }

    // ---- Phase 3: scale + bias(frag LDG, L1-hot) + padded mask + reg softmax
    const char* bfp = (const char*)biasf + (h * 2 + sub) * 3584 + lane * 16;
    float inv0[2], inv1[2];
    #pragma unroll
    for (int mi = 0; mi < 2; mi++) {
        int i0 = sub * 32 + mi * 16 + g;
        int i1 = i0 + 8;
        const float* m0p = (const float*)(sm + MOFF + i0 * MSTRIDE);
        const float* m1p = (const float*)(sm + MOFF + i1 * MSTRIDE);
        int c0c = (mi * 7) >> 1;        // base chunk: 0 or 3
        uint4 bb[4];
        #pragma unroll
        for (int k = 0; k < 4; k++)
            bb[k] = *(const uint4*)(bfp + (c0c + k) * 512);
        #pragma unroll
        for (int nt = 0; nt < 7; nt++) {
            int e = mi * 7 + nt;
            const uint4& B = bb[(e >> 1) - c0c];
            uint32_t u0 = (e & 1) ? B.z : B.x;
            uint32_t u1 = (e & 1) ? B.w : B.y;
            float2 bf0 = __half22float2(*reinterpret_cast<__half2*>(&u0));
            float2 bf1 = __half22float2(*reinterpret_cast<__half2*>(&u1));
            int j0 = nt * 8 + 2 * q;
            c[mi][nt][0] = c[mi][nt][0] * SCALE_F + bf0.x + m0p[j0];
            c[mi][nt][1] = c[mi][nt][1] * SCALE_F + bf0.y + m0p[j0 + 1];
            c[mi][nt][2] = c[mi][nt][2] * SCALE_F + bf1.x + m1p[j0];
            c[mi][nt][3] = c[mi][nt][3] * SCALE_F + bf1.y + m1p[j0 + 1];
        }
        float m0 = -1e30f, m1 = -1e30f;
        #pragma unroll
        for (int nt = 0; nt < 7; nt++) {
            m0 = fmaxf(m0, fmaxf(c[mi][nt][0], c[mi][nt][1]));
            m1 = fmaxf(m1, fmaxf(c[mi][nt][2], c[mi][nt][3]));
        }
        m0 = fmaxf(m0, __shfl_xor_sync(0xffffffffu, m0, 1));
        m0 = fmaxf(m0, __shfl_xor_sync(0xffffffffu, m0, 2));
        m1 = fmaxf(m1, __shfl_xor_sync(0xffffffffu, m1, 1));
        m1 = fmaxf(m1, __shfl_xor_sync(0xffffffffu, m1, 2));
        float s0 = 0.f, s1 = 0.f;
        #pragma unroll
        for (int nt = 0; nt < 7; nt++) {
            c[mi][nt][0] = __expf(c[mi][nt][0] - m0); s0 += c[mi][nt][0];
            c[mi][nt][1] = __expf(c[mi][nt][1] - m0); s0 += c[mi][nt][1];
            c[mi][nt][2] = __expf(c[mi][nt][2] - m1); s1 += c[mi][nt][2];
            c[mi][nt][3] = __expf(c[mi][nt][3] - m1); s1 += c[mi][nt][3];
        }
        s0 += __shfl_xor_sync(0xffffffffu, s0, 1);
        s0 += __shfl_xor_sync(0xffffffffu, s0, 2);
        s1 += __shfl_xor_sync(0xffffffffu, s1, 1);
        s1 += __shfl_xor_sync(0xffffffffu, s1, 2);
        inv0[mi] = 1.f / s0;
        inv1[mi] = 1.f / s1;
    }

    // ---- Pack P into fp16 A-fragments (registers only)
    uint32_t pa[2][4][4];
    #pragma unroll
    for (int mi = 0; mi < 2; mi++) {
        #pragma unroll
        for (int ch = 0; ch < 4; ch++) {
            int nt0 = 2 * ch, nt1 = 2 * ch + 1;
            pa[mi][ch][0] = pack_h2(c[mi][nt0][0] * inv0[mi], c[mi][nt0][1] * inv0[mi]);
            pa[mi][ch][1] = pack_h2(c[mi][nt0][2] * inv1[mi], c[mi][nt0][3] * inv1[mi]);
            if (nt1 < 7) {
                pa[mi][ch][2] = pack_h2(c[mi][nt1][0] * inv0[mi], c[mi][nt1][1] * inv0[mi]);
                pa[mi][ch][3] = pack_h2(c[mi][nt1][2] * inv1[mi], c[mi][nt1][3] * inv1[mi]);
            } else {
                pa[mi][ch][2] = 0u;
                pa[mi][ch][3] = 0u;
            }
        }
    }

    // ---- Phase 4: PV mma; B-frags via ldmatrix.trans on V region
    #pragma unroll
    for (int mi = 0; mi < 2; mi++) {
        int i0 = sub * 32 + mi * 16 + g;
        int i1 = i0 + 8;
        #pragma unroll
        for (int ni = 0; ni < 4; ni++) {
            float o[4] = {0.f, 0.f, 0.f, 0.f};
            #pragma unroll
            for (int hf = 0; hf < 2; hf++) {
                uint32_t addr = sbase + VOFF + (uint32_t)(hf * 32 + lane) * QKV_STRIDE
                              + hoff + ni * 16;
                uint32_t r0, r1, r2, r3;
                ldsm_x4_trans(r0, r1, r2, r3, addr);
                mma_f16(o, pa[mi][2 * hf][0], pa[mi][2 * hf][1],
                        pa[mi][2 * hf][2], pa[mi][2 * hf][3], r0, r1);
                mma_f16(o, pa[mi][2 * hf + 1][0], pa[mi][2 * hf + 1][1],
                        pa[mi][2 * hf + 1][2], pa[mi][2 * hf + 1][3], r2, r3);
            }
            int colb = (h * 32 + ni * 8) * 2 + q * 4;
            *(uint32_t*)(sm + AOOFF + i0 * AO_STRIDE + colb) = pack_h2(o[0], o[1]);
            *(uint32_t*)(sm + AOOFF + i1 * AO_STRIDE + colb) = pack_h2(o[2], o[3]);
        }
    }
    __syncthreads();

    // ---- Phase 5: proj GEMM [64x256] = AO[64x256] x W2T[256x256]^T (R9 form)
    const int wm   = wid & 1;
    const int wcol = wid >> 1;         // 0..7
    float d[2][4][4];
    #pragma unroll
    for (int mi = 0; mi < 2; mi++)
        #pragma unroll
        for (int ni = 0; ni < 4; ni++)
            #pragma unroll
            for (int r = 0; r < 4; r++) d[mi][ni][r] = 0.f;

    #pragma unroll
    for (int cp = 0; cp < 8; cp++) {
        uint4 ra[2], rb[2];
        #pragma unroll
        for (int mi = 0; mi < 2; mi++) {
            int r0 = wm * 32 + mi * 16 + g;
            ra[mi] = *(const uint4*)(sm + AOOFF + r0 * AO_STRIDE + cp * 64 + q * 16);
            rb[mi] = *(const uint4*)(sm + AOOFF + (r0 + 8) * AO_STRIDE + cp * 64 + q * 16);
        }
        #pragma unroll
        for (int ni = 0; ni < 4; ni++) {
            int n = wcol * 32 + ni * 8 + g;
            uint4 sb = *(const uint4*)(w2 + (size_t)n * KDIM + cp * 32 + q * 8);
            #pragma unroll
            for (int mi = 0; mi < 2; mi++) {
                mma_f16(d[mi][ni], ra[mi].x, rb[mi].x, ra[mi].y, rb[mi].y, sb.x, sb.y);
                mma_f16(d[mi][ni], ra[mi].z, rb[mi].z, ra[mi].w, rb[mi].w, sb.z, sb.w);
            }
        }
    }

    // ---- Epilogue: + proj_b, fp32 out (valid rows only)
    #pragma unroll
    for (int mi = 0; mi < 2; mi++) {
        int i0 = wm * 32 + mi * 16 + g;
        int i1 = i0 + 8;
        #pragma unroll
        for (int ni = 0; ni < 4; ni++) {
            int n0 = wcol * 32 + ni * 8 + 2 * q;
            float2 pb = *(const float2*)(proj_b + n0);
            if (i0 < NTOK) {
                float2 v = make_float2(d[mi][ni][0] + pb.x, d[mi][ni][1] + pb.y);
                *(float2*)(out + ((size_t)b * NTOK + i0) * DIM + n0) = v;
            }
            if (i1 < NTOK) {
                float2 v = make_float2(d[mi][ni][2] + pb.x, d[mi][ni][3] + pb.y);
                *(float2*)(out + ((size_t)b * NTOK + i1) * DIM + n0) = v;
            }
        }
    }
}

// ---------------------------------------------------------------------------
extern "C" void kernel_launch(void* const* d_in, const int* in_sizes, int n_in,
                              void* d_out, int out_size)
{
    const float* x      = (const float*)d_in[0];
    const float* mask   = (const float*)d_in[1];
    const float* qkv_w  = (const float*)d_in[2];
    const float* qkv_b  = (const float*)d_in[3];
    const float* rpb    = (const float*)d_in[4];
    const float* proj_w = (const float*)d_in[5];
    const float* proj_b = (const float*)d_in[6];
    float* out = (float*)d_out;

    __half *xh, *qkvh, *w1h, *w2h, *biasf;
    cudaGetSymbolAddress((void**)&xh, g_xh);
    cudaGetSymbolAddress((void**)&qkvh, g_qkvh);
    cudaGetSymbolAddress((void**)&w1h, g_w1h);
    cudaGetSymbolAddress((void**)&w2h, g_w2h);
    cudaGetSymbolAddress((void**)&biasf, g_biasf);

    cudaFuncSetAttribute(gemm_h,
                         cudaFuncAttributeMaxDynamicSharedMemorySize, GEMM_SMEM_H);
    cudaFuncSetAttribute(attn_proj_fused,
                         cudaFuncAttributeMaxDynamicSharedMemorySize, FUSE_SMEM);

    // 0) Pre-passes
    int n4 = MTOK * DIM / 4;
    f2h_kernel<<<(n4 + 255) / 256, 256>>>(x, xh, n4);
    prep_kernel<<<(PREP_TOTAL + 255) / 256, 256>>>(qkv_w, proj_w, rpb,
                                                   w1h, w2h, biasf);

    // 1) QKV GEMM (fp16)
    gemm_h<<<dim3(QKV_N / 128, MTOK / 128), 256, GEMM_SMEM_H>>>(
        xh, w1h, qkv_b, qkvh, QKV_N);

    // 2) Fused attention + projection (fp32 out)
    attn_proj_fused<<<BATCH, 512, FUSE_SMEM>>>(
        qkvh, mask, biasf, w2h, proj_b, out);
}